// round 2
// baseline (speedup 1.0000x reference)
#include <cuda_runtime.h>
#include <cstdint>

#define Bsz 2048
#define Tt  100
#define Uu  512
#define Cc  10
#define G4  2048   // 4*U

// GEMM tiling
#define BM      128      // batch rows per CTA
#define BN_U    64       // hidden units per CTA (x4 gates = 256 z cols)
#define BK      32       // k per smem tile
#define THREADS 512      // 16 warps = 4 rowWarps x 4 colWarps

#define A_STRIDE 36      // BK + 4 pad (floats)
#define B_STRIDE 264     // 256 + 8 pad (floats)

// ---------------- device state (static allocation is allowed) ----------------
__device__ float g_h[3][2][Bsz * Uu];      // ping-pong h per layer
__device__ float g_c[3][Bsz * Uu];         // c per layer (in-place safe)
__device__ float g_wr0[512  * G4];         // tf32-rounded U0
__device__ float g_wr1[1024 * G4];         // tf32-rounded [W1;U1]
__device__ float g_wr2[1024 * G4];         // tf32-rounded [W2;U2]

// ---------------- helpers ----------------
__device__ __forceinline__ unsigned f2tf32(float f) {
    unsigned u;
    asm("cvt.rna.tf32.f32 %0, %1;" : "=r"(u) : "f"(f));
    return u;
}

__device__ __forceinline__ void mma_tf32(float* d, const unsigned* a, const unsigned* b) {
    asm volatile(
        "mma.sync.aligned.m16n8k8.row.col.f32.tf32.tf32.f32 "
        "{%0,%1,%2,%3}, {%4,%5,%6,%7}, {%8,%9}, {%0,%1,%2,%3};"
        : "+f"(d[0]), "+f"(d[1]), "+f"(d[2]), "+f"(d[3])
        : "r"(a[0]), "r"(a[1]), "r"(a[2]), "r"(a[3]), "r"(b[0]), "r"(b[1]));
}

__device__ __forceinline__ void cp16(unsigned dst, const void* src) {
    asm volatile("cp.async.cg.shared.global [%0], [%1], 16;" ::"r"(dst), "l"(src));
}

__device__ __forceinline__ float fsigmoid(float x) { return 1.0f / (1.0f + __expf(-x)); }
__device__ __forceinline__ float ftanh(float x)    { return 1.0f - 2.0f / (__expf(2.0f * x) + 1.0f); }

// ---------------- prep kernels ----------------
__global__ void zero_state_kernel() {
    int n = Bsz * Uu;
    for (int i = blockIdx.x * blockDim.x + threadIdx.x; i < 3 * n; i += gridDim.x * blockDim.x) {
        int l = i / n, r = i % n;
        g_h[l][0][r] = 0.0f;
        g_c[l][r]    = 0.0f;
    }
}

// Build tf32-rounded concatenated weight matrix [K x 2048] for one layer.
__global__ void wprep_kernel(const float* __restrict__ W, const float* __restrict__ Uw, int layer) {
    int K   = (layer == 0) ? 512 : 1024;
    int Klo = (layer == 0) ? 0 : 512;
    float* dst = (layer == 0) ? g_wr0 : ((layer == 1) ? g_wr1 : g_wr2);
    int total = K * G4;
    for (int idx = blockIdx.x * blockDim.x + threadIdx.x; idx < total; idx += gridDim.x * blockDim.x) {
        int k = idx >> 11, c = idx & 2047;
        float v = (k < Klo) ? W[k * G4 + c] : Uw[(k - Klo) * G4 + c];
        ((unsigned*)dst)[idx] = f2tf32(v);
    }
}

// ---------------- fused LSTM layer step ----------------
// z = [h_below ; h_own] @ Wr + bias (+ x_t * W0 for layer 0)  -> gates -> masked h,c update
__global__ void __launch_bounds__(THREADS, 1)
lstm_layer_kernel(const float* __restrict__ x, const int* __restrict__ mask,
                  const float* __restrict__ bias, const float* __restrict__ W0,
                  int layer, int t)
{
    const int K   = (layer == 0) ? 512 : 1024;
    const int Klo = (layer == 0) ? 0 : 512;
    const float* Wr = (layer == 0) ? g_wr0 : ((layer == 1) ? g_wr1 : g_wr2);
    const int p = t & 1;
    const float* Hold = g_h[layer][p];
    float*       Hnew = g_h[layer][p ^ 1];
    const float* Alo  = (layer == 0) ? (const float*)0 : g_h[layer - 1][p ^ 1];
    float*       Cst  = g_c[layer];

    extern __shared__ float smem[];
    float* As[2] = { smem, smem + BM * A_STRIDE };
    float* Bs[2] = { smem + 2 * BM * A_STRIDE, smem + 2 * BM * A_STRIDE + BK * B_STRIDE };

    const int tid  = threadIdx.x;
    const int lane = tid & 31, warp = tid >> 5;
    const int colWarp = warp & 3, rowWarp = warp >> 2;
    const int g = lane >> 2, tig = lane & 3;
    const int row0 = blockIdx.y * BM;
    const int u0   = blockIdx.x * BN_U;

    float acc[2][8][4];
#pragma unroll
    for (int m = 0; m < 2; m++)
#pragma unroll
        for (int j = 0; j < 8; j++)
#pragma unroll
            for (int r = 0; r < 4; r++) acc[m][j][r] = 0.0f;

    const int nt = K / BK;

    // ---- tile load lambdas (manually inlined) ----
    // A: 128 rows x 32 k, 2 float4 per thread, rounded to tf32 at STS time.
    // B: 32 k x 256 cols (4 gate chunks of 64), 4 cp.async per thread.

    // preload tile 0
    {
        int kbase = 0;
        const float* src = (kbase < Klo) ? Alo : Hold;
        int koff = (kbase < Klo) ? kbase : kbase - Klo;
#pragma unroll
        for (int i = 0; i < 2; i++) {
            int c = i * 512 + tid;
            int r = c >> 3, k4 = c & 7;
            float4 v = *(const float4*)&src[(size_t)(row0 + r) * Uu + koff + k4 * 4];
            uint4 u;
            u.x = f2tf32(v.x); u.y = f2tf32(v.y); u.z = f2tf32(v.z); u.w = f2tf32(v.w);
            *(uint4*)&As[0][r * A_STRIDE + k4 * 4] = u;
        }
#pragma unroll
        for (int i = 0; i < 4; i++) {
            int c = i * 512 + tid;
            int r = c >> 6, col = (c & 63) * 4;
            int gate = col >> 6, ul = col & 63;
            const float* bsrc = &Wr[(size_t)(kbase + r) * G4 + gate * 512 + u0 + ul];
            unsigned dst = (unsigned)__cvta_generic_to_shared(&Bs[0][r * B_STRIDE + col]);
            cp16(dst, bsrc);
        }
        asm volatile("cp.async.commit_group;");
        asm volatile("cp.async.wait_group 0;");
        __syncthreads();
    }

    for (int kt = 0; kt < nt; kt++) {
        int st = kt & 1;
        bool hasNext = (kt + 1 < nt);
        float4 areg[2];
        if (hasNext) {
            int kbase = (kt + 1) * BK;
            const float* src = (kbase < Klo) ? Alo : Hold;
            int koff = (kbase < Klo) ? kbase : kbase - Klo;
#pragma unroll
            for (int i = 0; i < 2; i++) {
                int c = i * 512 + tid;
                int r = c >> 3, k4 = c & 7;
                areg[i] = *(const float4*)&src[(size_t)(row0 + r) * Uu + koff + k4 * 4];
            }
#pragma unroll
            for (int i = 0; i < 4; i++) {
                int c = i * 512 + tid;
                int r = c >> 6, col = (c & 63) * 4;
                int gate = col >> 6, ul = col & 63;
                const float* bsrc = &Wr[(size_t)(kbase + r) * G4 + gate * 512 + u0 + ul];
                unsigned dst = (unsigned)__cvta_generic_to_shared(&Bs[st ^ 1][r * B_STRIDE + col]);
                cp16(dst, bsrc);
            }
            asm volatile("cp.async.commit_group;");
        }

        // ---- compute current tile ----
        const unsigned* Asm = (const unsigned*)As[st];
        const unsigned* Bsm = (const unsigned*)Bs[st];
#pragma unroll
        for (int ks = 0; ks < BK; ks += 8) {
            unsigned af[2][4];
            unsigned bf[8][2];
#pragma unroll
            for (int m = 0; m < 2; m++) {
                int rb = rowWarp * 32 + m * 16;
                af[m][0] = Asm[(rb + g)     * A_STRIDE + ks + tig];
                af[m][1] = Asm[(rb + g + 8) * A_STRIDE + ks + tig];
                af[m][2] = Asm[(rb + g)     * A_STRIDE + ks + tig + 4];
                af[m][3] = Asm[(rb + g + 8) * A_STRIDE + ks + tig + 4];
            }
#pragma unroll
            for (int j = 0; j < 8; j++) {
                int colb = (j >> 1) * 64 + colWarp * 16 + (j & 1) * 8;
                bf[j][0] = Bsm[(ks + tig)     * B_STRIDE + colb + g];
                bf[j][1] = Bsm[(ks + tig + 4) * B_STRIDE + colb + g];
            }
#pragma unroll
            for (int m = 0; m < 2; m++)
#pragma unroll
                for (int j = 0; j < 8; j++)
                    mma_tf32(acc[m][j], af[m], bf[j]);
        }

        if (hasNext) {
#pragma unroll
            for (int i = 0; i < 2; i++) {
                int c = i * 512 + tid;
                int r = c >> 3, k4 = c & 7;
                uint4 u;
                u.x = f2tf32(areg[i].x); u.y = f2tf32(areg[i].y);
                u.z = f2tf32(areg[i].z); u.w = f2tf32(areg[i].w);
                *(uint4*)&As[st ^ 1][r * A_STRIDE + k4 * 4] = u;
            }
            asm volatile("cp.async.wait_group 0;");
        }
        __syncthreads();
    }

    // ---- fused epilogue: gates + mask + state update ----
#pragma unroll
    for (int m = 0; m < 2; m++) {
#pragma unroll
        for (int rs = 0; rs < 2; rs++) {
            int b = row0 + rowWarp * 32 + m * 16 + g + rs * 8;
            int mk = mask[b * Tt + t];
            float xv = (layer == 0) ? x[b * Tt + t] : 0.0f;
#pragma unroll
            for (int half = 0; half < 2; half++) {
#pragma unroll
                for (int pp = 0; pp < 2; pp++) {
                    int u  = u0 + colWarp * 16 + half * 8 + tig * 2 + pp;
                    int ri = rs * 2 + pp;
                    float zi = acc[m][0 + half][ri] + bias[u];
                    float zf = acc[m][2 + half][ri] + bias[512 + u];
                    float zg = acc[m][4 + half][ri] + bias[1024 + u];
                    float zo = acc[m][6 + half][ri] + bias[1536 + u];
                    if (layer == 0) {
                        zi += xv * W0[u];
                        zf += xv * W0[512 + u];
                        zg += xv * W0[1024 + u];
                        zo += xv * W0[1536 + u];
                    }
                    int   si = b * Uu + u;
                    float co = Cst[si], ho = Hold[si];
                    float ig = fsigmoid(zi);
                    float fg = fsigmoid(zf);
                    float gg = ftanh(zg);
                    float og = fsigmoid(zo);
                    float cn = fg * co + ig * gg;
                    float hn = og * ftanh(cn);
                    if (!mk) { cn = co; hn = ho; }
                    Cst[si]  = cn;
                    Hnew[si] = hn;
                }
            }
        }
    }
}

// ---------------- softmax head ----------------
__global__ void head_kernel(const float* __restrict__ Wd, const float* __restrict__ bd,
                            float* __restrict__ out)
{
    int gw   = (blockIdx.x * blockDim.x + threadIdx.x) >> 5;
    int lane = threadIdx.x & 31;
    if (gw >= Bsz) return;
    const float* h = &g_h[2][0][(size_t)gw * Uu];   // T=100 even -> final states in buffer 0
    float a[Cc];
#pragma unroll
    for (int c = 0; c < Cc; c++) a[c] = 0.0f;
    for (int k = lane; k < Uu; k += 32) {
        float hv = h[k];
#pragma unroll
        for (int c = 0; c < Cc; c++) a[c] += hv * Wd[k * Cc + c];
    }
#pragma unroll
    for (int c = 0; c < Cc; c++)
#pragma unroll
        for (int off = 16; off > 0; off >>= 1)
            a[c] += __shfl_xor_sync(0xffffffffu, a[c], off);
    if (lane == 0) {
        float logit[Cc], mx = -1e30f;
#pragma unroll
        for (int c = 0; c < Cc; c++) { logit[c] = a[c] + bd[c]; mx = fmaxf(mx, logit[c]); }
        float s = 0.0f;
#pragma unroll
        for (int c = 0; c < Cc; c++) { logit[c] = expf(logit[c] - mx); s += logit[c]; }
        float inv = 1.0f / s;
#pragma unroll
        for (int c = 0; c < Cc; c++) out[gw * Cc + c] = logit[c] * inv;
    }
}

// ---------------- launch ----------------
extern "C" void kernel_launch(void* const* d_in, const int* in_sizes, int n_in,
                              void* d_out, int out_size)
{
    const float* x    = (const float*)d_in[0];
    const int*   mask = (const int*)  d_in[1];
    const float* W0   = (const float*)d_in[2];
    const float* U0   = (const float*)d_in[3];
    const float* b0   = (const float*)d_in[4];
    const float* W1   = (const float*)d_in[5];
    const float* U1   = (const float*)d_in[6];
    const float* b1   = (const float*)d_in[7];
    const float* W2   = (const float*)d_in[8];
    const float* U2   = (const float*)d_in[9];
    const float* b2   = (const float*)d_in[10];
    const float* Wd   = (const float*)d_in[11];
    const float* bd   = (const float*)d_in[12];
    float* out = (float*)d_out;

    size_t smem_bytes = (size_t)(2 * BM * A_STRIDE + 2 * BK * B_STRIDE) * sizeof(float);
    cudaFuncSetAttribute(lstm_layer_kernel, cudaFuncAttributeMaxDynamicSharedMemorySize,
                         (int)smem_bytes);

    zero_state_kernel<<<256, 256>>>();
    wprep_kernel<<<256, 256>>>((const float*)0, U0, 0);
    wprep_kernel<<<512, 256>>>(W1, U1, 1);
    wprep_kernel<<<512, 256>>>(W2, U2, 2);

    dim3 grid(8, 16);   // 8 u-tiles x 16 row-tiles = 128 CTAs
    for (int t = 0; t < Tt; t++) {
        lstm_layer_kernel<<<grid, THREADS, smem_bytes>>>(x, mask, b0, W0, 0, t);
        lstm_layer_kernel<<<grid, THREADS, smem_bytes>>>(x, mask, b1, (const float*)0, 1, t);
        lstm_layer_kernel<<<grid, THREADS, smem_bytes>>>(x, mask, b2, (const float*)0, 2, t);
    }
    head_kernel<<<(Bsz * 32 + 255) / 256, 256>>>(Wd, bd, out);
}

// round 3
// speedup vs baseline: 1.4095x; 1.4095x over previous
#include <cuda_runtime.h>
#include <cuda_bf16.h>
#include <cstdint>

#define Bsz 2048
#define Tt  100
#define Uu  512
#define Cc  10
#define G4  2048   // 4*U

// GEMM tiling
#define BM      128      // batch rows per CTA
#define BN      256      // z-columns per CTA (= 64 hidden units x 4 gates)
#define BKH     64       // k (halves) per stage
#define THREADS 512      // 16 warps = 4 rowWarps x 4 colWarps
#define NS      3        // pipeline stages

#define A_BYTES 16384    // 128 rows x 128B
#define B_BYTES 32768    // 256 cols x 128B
#define STAGE_BYTES (A_BYTES + B_BYTES)
#define HBLK    262144   // one k-chunk block of h: 2048 rows x 128B
#define SMEM_DATA_OFF 1024
#define SMEM_TOTAL (SMEM_DATA_OFF + NS * STAGE_BYTES)

// ---------------- device state ----------------
__device__ __nv_bfloat16 g_h[3][2][Bsz * Uu];   // ping-pong h, k-tiled + swizzled layout
__device__ float         g_c[3][Bsz * Uu];      // c fp32, linear
__device__ __nv_bfloat16 g_w0[512  * G4];       // tiled+swizzled bf16 weights
__device__ __nv_bfloat16 g_w1[1024 * G4];
__device__ __nv_bfloat16 g_w2[1024 * G4];

// ---------------- helpers ----------------
__device__ __forceinline__ void mbar_init(uint32_t a, uint32_t cnt) {
    asm volatile("mbarrier.init.shared::cta.b64 [%0], %1;" ::"r"(a), "r"(cnt) : "memory");
}
__device__ __forceinline__ void mbar_arrive(uint32_t a) {
    asm volatile("mbarrier.arrive.shared::cta.b64 _, [%0];" ::"r"(a) : "memory");
}
__device__ __forceinline__ void mbar_expect_tx(uint32_t a, uint32_t bytes) {
    asm volatile("mbarrier.arrive.expect_tx.shared::cta.b64 _, [%0], %1;" ::"r"(a), "r"(bytes) : "memory");
}
__device__ __forceinline__ void mbar_wait(uint32_t a, uint32_t parity) {
    asm volatile(
        "{\n\t"
        ".reg .pred P;\n\t"
        "WL%=:\n\t"
        "mbarrier.try_wait.parity.acquire.cta.shared::cta.b64 P, [%0], %1, 0x989680;\n\t"
        "@P bra WD%=;\n\t"
        "bra WL%=;\n\t"
        "WD%=:\n\t"
        "}" ::"r"(a), "r"(parity) : "memory");
}
__device__ __forceinline__ void bulk_g2s(uint32_t dst, const void* src, uint32_t bytes, uint32_t mbar) {
    asm volatile(
        "cp.async.bulk.shared::cluster.global.mbarrier::complete_tx::bytes [%0], [%1], %2, [%3];"
        ::"r"(dst), "l"(src), "r"(bytes), "r"(mbar) : "memory");
}
__device__ __forceinline__ void mma_bf16(float* d, const unsigned* a, const unsigned* b) {
    asm volatile(
        "mma.sync.aligned.m16n8k16.row.col.f32.bf16.bf16.f32 "
        "{%0,%1,%2,%3}, {%4,%5,%6,%7}, {%8,%9}, {%0,%1,%2,%3};"
        : "+f"(d[0]), "+f"(d[1]), "+f"(d[2]), "+f"(d[3])
        : "r"(a[0]), "r"(a[1]), "r"(a[2]), "r"(a[3]), "r"(b[0]), "r"(b[1]));
}
__device__ __forceinline__ float fsigmoid(float x) { return 1.0f / (1.0f + __expf(-x)); }
__device__ __forceinline__ float ftanh(float x)    { return 1.0f - 2.0f / (__expf(2.0f * x) + 1.0f); }

// ---------------- prep kernels ----------------
__global__ void zero_state_kernel() {
    int nh = 3 * 2 * Bsz * Uu;      // bf16 elements
    int nc = 3 * Bsz * Uu;          // fp32 elements
    __nv_bfloat16* h = &g_h[0][0][0];
    float* c = &g_c[0][0];
    for (int i = blockIdx.x * blockDim.x + threadIdx.x; i < nh; i += gridDim.x * blockDim.x)
        h[i] = __float2bfloat16(0.0f);
    for (int i = blockIdx.x * blockDim.x + threadIdx.x; i < nc; i += gridDim.x * blockDim.x)
        c[i] = 0.0f;
}

// Build tiled + SW128-preswizzled bf16 weight blocks.
// Block (nt, kt): 256 cols x 64 k, [col][k] layout, 32KB each.
__global__ void wprep_kernel(const float* __restrict__ W, const float* __restrict__ Uw, int layer) {
    int K   = (layer == 0) ? 512 : 1024;
    int Klo = (layer == 0) ? 0 : 512;
    int nkt = K / 64;
    char* dst = (char*)((layer == 0) ? g_w0 : ((layer == 1) ? g_w1 : g_w2));
    int totalPairs = K * G4 / 2;
    for (int idx = blockIdx.x * blockDim.x + threadIdx.x; idx < totalPairs;
         idx += gridDim.x * blockDim.x) {
        int klp = idx & 31;           // k-pair within 64
        int c   = (idx >> 5) & 255;   // col within tile
        int blk = idx >> 13;
        int kt  = blk % nkt;
        int nt  = blk / nkt;
        int z   = (c >> 6) * 512 + nt * 64 + (c & 63);
        int kg  = kt * 64 + klp * 2;
        float v0, v1;
        if (kg < Klo) { v0 = W[kg * G4 + z]; v1 = W[(kg + 1) * G4 + z]; }
        else          { v0 = Uw[(kg - Klo) * G4 + z]; v1 = Uw[(kg + 1 - Klo) * G4 + z]; }
        uint32_t off = (uint32_t)(nt * nkt + kt) * B_BYTES + c * 128 +
                       (((uint32_t)klp * 4) ^ (((uint32_t)c & 7) * 16));
        *(__nv_bfloat162*)(dst + off) = __floats2bfloat162_rn(v0, v1);
    }
}

// ---------------- fused LSTM layer step ----------------
__global__ void __launch_bounds__(THREADS, 1)
lstm_layer_kernel(const float* __restrict__ x, const int* __restrict__ mask,
                  const float* __restrict__ bias, const float* __restrict__ W0,
                  int layer, int t)
{
    const int K   = (layer == 0) ? 512 : 1024;
    const int nkt = K / 64;
    const char* wB = (const char*)((layer == 0) ? g_w0 : ((layer == 1) ? g_w1 : g_w2));
    const int p = t & 1;
    const char* hOwnOld = (const char*)g_h[layer][p];
    char*       hOwnNew = (char*)g_h[layer][p ^ 1];
    const char* hLow    = (layer == 0) ? hOwnOld : (const char*)g_h[layer - 1][p ^ 1];
    float*      Cst     = g_c[layer];

    extern __shared__ char smem[];
    const uint32_t sbase = (uint32_t)__cvta_generic_to_shared(smem);
    const uint32_t sdata = sbase + SMEM_DATA_OFF;

    const int tid  = threadIdx.x;
    const int lane = tid & 31, warp = tid >> 5;
    const int colWarp = warp & 3, rowWarp = warp >> 2;
    const int g = lane >> 2, tig = lane & 3;
    const int row0 = blockIdx.y * BM;
    const int nt   = blockIdx.x;
    const int u0   = nt * 64;

    // barriers: full[s] at sbase + s*16, empty[s] at +8
    if (tid == 0) {
        for (int s = 0; s < NS; s++) {
            mbar_init(sbase + s * 16, 1);        // full: producer expect_tx arrival
            mbar_init(sbase + s * 16 + 8, 16);   // empty: one arrive per warp
        }
        asm volatile("fence.proxy.async.shared::cta;" ::: "memory");
    }
    __syncthreads();

    auto issue_tile = [&](int kt) {
        int s = kt % NS;
        uint32_t full = sbase + s * 16;
        mbar_expect_tx(full, STAGE_BYTES);
        const char* asrc = (kt < 8) ? (hLow + (size_t)kt * HBLK)
                                    : (hOwnOld + (size_t)(kt - 8) * HBLK);
        asrc += (size_t)row0 * 128;
        bulk_g2s(sdata + s * STAGE_BYTES, asrc, A_BYTES, full);
        const char* bsrc = wB + (size_t)(nt * nkt + kt) * B_BYTES;
        bulk_g2s(sdata + s * STAGE_BYTES + A_BYTES, bsrc, B_BYTES, full);
    };

    if (tid == 0)
        for (int s = 0; s < NS && s < nkt; s++) issue_tile(s);

    float acc[2][8][4];
#pragma unroll
    for (int m = 0; m < 2; m++)
#pragma unroll
        for (int j = 0; j < 8; j++)
#pragma unroll
            for (int r = 0; r < 4; r++) acc[m][j][r] = 0.0f;

    const uint32_t msk = (uint32_t)g * 16;

    for (int kt = 0; kt < nkt; kt++) {
        int s = kt % NS;
        mbar_wait(sbase + s * 16, (uint32_t)((kt / NS) & 1));

        const char* As = smem + SMEM_DATA_OFF + s * STAGE_BYTES;
        const char* Bs = As + A_BYTES;

#pragma unroll
        for (int kq = 0; kq < 4; kq++) {
            const uint32_t kb0 = (uint32_t)kq * 32 + (uint32_t)tig * 4;  // a0/b0 byte-in-row
            unsigned af[2][4];
#pragma unroll
            for (int m = 0; m < 2; m++) {
                int lr = rowWarp * 32 + m * 16 + g;
                const char* r0p = As + lr * 128;
                const char* r8p = r0p + 8 * 128;
                af[m][0] = *(const unsigned*)(r0p + (kb0 ^ msk));
                af[m][1] = *(const unsigned*)(r8p + (kb0 ^ msk));
                af[m][2] = *(const unsigned*)(r0p + ((kb0 + 16) ^ msk));
                af[m][3] = *(const unsigned*)(r8p + ((kb0 + 16) ^ msk));
            }
            unsigned bf[8][2];
#pragma unroll
            for (int j = 0; j < 8; j++) {
                int cb = (j >> 1) * 64 + colWarp * 16 + (j & 1) * 8 + g;
                const char* cp = Bs + cb * 128;
                bf[j][0] = *(const unsigned*)(cp + (kb0 ^ msk));
                bf[j][1] = *(const unsigned*)(cp + ((kb0 + 16) ^ msk));
            }
#pragma unroll
            for (int m = 0; m < 2; m++)
#pragma unroll
                for (int j = 0; j < 8; j++)
                    mma_bf16(acc[m][j], af[m], bf[j]);
        }

        if (lane == 0) mbar_arrive(sbase + s * 16 + 8);
        if (tid == 0 && kt + NS < nkt) {
            mbar_wait(sbase + s * 16 + 8, (uint32_t)((kt / NS) & 1));
            issue_tile(kt + NS);
        }
    }

    // ---- fused epilogue: gates + mask + state update ----
#pragma unroll
    for (int m = 0; m < 2; m++) {
#pragma unroll
        for (int rs = 0; rs < 2; rs++) {
            int b = row0 + rowWarp * 32 + m * 16 + g + rs * 8;
            int mk = mask[b * Tt + t];
            float xv = (layer == 0) ? x[b * Tt + t] : 0.0f;
            uint32_t bsw = ((uint32_t)b & 7) * 16;
#pragma unroll
            for (int half = 0; half < 2; half++) {
                int ubase = u0 + colWarp * 16 + half * 8 + tig * 2;  // even
                uint32_t hoff = (uint32_t)(ubase >> 6) * HBLK + (uint32_t)b * 128 +
                                ((((uint32_t)ubase & 63) * 2) ^ bsw);
                __nv_bfloat162 hold2 = *(const __nv_bfloat162*)(hOwnOld + hoff);
                float hn2[2];
#pragma unroll
                for (int pp = 0; pp < 2; pp++) {
                    int u  = ubase + pp;
                    int ri = rs * 2 + pp;
                    float zi = acc[m][0 + half][ri] + bias[u];
                    float zf = acc[m][2 + half][ri] + bias[512 + u];
                    float zg = acc[m][4 + half][ri] + bias[1024 + u];
                    float zo = acc[m][6 + half][ri] + bias[1536 + u];
                    if (layer == 0) {
                        zi += xv * W0[u];
                        zf += xv * W0[512 + u];
                        zg += xv * W0[1024 + u];
                        zo += xv * W0[1536 + u];
                    }
                    int   si = b * Uu + u;
                    float co = Cst[si];
                    float ig = fsigmoid(zi);
                    float fg = fsigmoid(zf);
                    float gg = ftanh(zg);
                    float og = fsigmoid(zo);
                    float cn = fg * co + ig * gg;
                    float hn = og * ftanh(cn);
                    if (!mk) {
                        cn = co;
                        hn = __bfloat162float(pp ? hold2.y : hold2.x);
                    }
                    Cst[si] = cn;
                    hn2[pp] = hn;
                }
                *(__nv_bfloat162*)(hOwnNew + hoff) = __floats2bfloat162_rn(hn2[0], hn2[1]);
            }
        }
    }
}

// ---------------- softmax head ----------------
__global__ void head_kernel(const float* __restrict__ Wd, const float* __restrict__ bd,
                            float* __restrict__ out)
{
    int gw   = (blockIdx.x * blockDim.x + threadIdx.x) >> 5;
    int lane = threadIdx.x & 31;
    if (gw >= Bsz) return;
    const char* h = (const char*)g_h[2][0];   // T even -> final states in buffer 0
    uint32_t bsw = ((uint32_t)gw & 7) * 16;
    float a[Cc];
#pragma unroll
    for (int c = 0; c < Cc; c++) a[c] = 0.0f;
    for (int k = lane; k < Uu; k += 32) {
        uint32_t off = (uint32_t)(k >> 6) * HBLK + (uint32_t)gw * 128 +
                       ((((uint32_t)k & 63) * 2) ^ bsw);
        float hv = __bfloat162float(*(const __nv_bfloat16*)(h + off));
#pragma unroll
        for (int c = 0; c < Cc; c++) a[c] += hv * Wd[k * Cc + c];
    }
#pragma unroll
    for (int c = 0; c < Cc; c++)
#pragma unroll
        for (int off = 16; off > 0; off >>= 1)
            a[c] += __shfl_xor_sync(0xffffffffu, a[c], off);
    if (lane == 0) {
        float logit[Cc], mx = -1e30f;
#pragma unroll
        for (int c = 0; c < Cc; c++) { logit[c] = a[c] + bd[c]; mx = fmaxf(mx, logit[c]); }
        float s = 0.0f;
#pragma unroll
        for (int c = 0; c < Cc; c++) { logit[c] = expf(logit[c] - mx); s += logit[c]; }
        float inv = 1.0f / s;
#pragma unroll
        for (int c = 0; c < Cc; c++) out[gw * Cc + c] = logit[c] * inv;
    }
}

// ---------------- launch ----------------
extern "C" void kernel_launch(void* const* d_in, const int* in_sizes, int n_in,
                              void* d_out, int out_size)
{
    const float* x    = (const float*)d_in[0];
    const int*   mask = (const int*)  d_in[1];
    const float* W0   = (const float*)d_in[2];
    const float* U0   = (const float*)d_in[3];
    const float* b0   = (const float*)d_in[4];
    const float* W1   = (const float*)d_in[5];
    const float* U1   = (const float*)d_in[6];
    const float* b1   = (const float*)d_in[7];
    const float* W2   = (const float*)d_in[8];
    const float* U2   = (const float*)d_in[9];
    const float* b2   = (const float*)d_in[10];
    const float* Wd   = (const float*)d_in[11];
    const float* bd   = (const float*)d_in[12];
    float* out = (float*)d_out;

    cudaFuncSetAttribute(lstm_layer_kernel, cudaFuncAttributeMaxDynamicSharedMemorySize,
                         SMEM_TOTAL);

    zero_state_kernel<<<256, 256>>>();
    wprep_kernel<<<256, 256>>>((const float*)0, U0, 0);
    wprep_kernel<<<512, 256>>>(W1, U1, 1);
    wprep_kernel<<<512, 256>>>(W2, U2, 2);

    dim3 grid(8, 16);   // 8 u-tiles x 16 row-tiles = 128 CTAs
    for (int t = 0; t < Tt; t++) {
        lstm_layer_kernel<<<grid, THREADS, SMEM_TOTAL>>>(x, mask, b0, W0, 0, t);
        lstm_layer_kernel<<<grid, THREADS, SMEM_TOTAL>>>(x, mask, b1, (const float*)0, 1, t);
        lstm_layer_kernel<<<grid, THREADS, SMEM_TOTAL>>>(x, mask, b2, (const float*)0, 2, t);
    }
    head_kernel<<<(Bsz * 32 + 255) / 256, 256>>>(Wd, bd, out);
}

// round 5
// speedup vs baseline: 4.3740x; 3.1033x over previous
#include <cuda_runtime.h>
#include <cuda_bf16.h>
#include <cstdint>

#define Bsz 2048
#define Tt  100
#define Uu  512
#define Cc  10
#define G4  2048   // 4*U

#define BM      64       // compacted batch rows per CTA
#define THREADS 256      // 8 warps = 2 rowWarps x 4 colWarps
#define NS      2        // pipeline stages

#define A_BYTES 8192     // 64 rows x 128B (64 bf16 k)
#define B_BYTES 32768    // 256 cols x 128B
#define STAGE_BYTES (A_BYTES + B_BYTES)     // 40960
#define SMEM_TOTAL (NS * STAGE_BYTES + 1024)

// ---------------- device state ----------------
__device__ __nv_bfloat16 g_h[3][2][Bsz * Uu];                 // ping-pong h, PLAIN [b][512]
__device__ float         g_c[3][Bsz * Uu];                     // c fp32, linear
__device__ __align__(1024) __nv_bfloat16 g_w0[512  * G4];      // tiled+swizzled bf16 weights
__device__ __align__(1024) __nv_bfloat16 g_w1[1024 * G4];
__device__ __align__(1024) __nv_bfloat16 g_w2[1024 * G4];
__device__ int g_order[Tt][Bsz];                               // per-t: active rows, then inactive
__device__ int g_count[Tt];

// ---------------- helpers ----------------
__device__ __forceinline__ void mbar_init(uint32_t a, uint32_t cnt) {
    asm volatile("mbarrier.init.shared::cta.b64 [%0], %1;" ::"r"(a), "r"(cnt) : "memory");
}
__device__ __forceinline__ void mbar_expect_tx(uint32_t a, uint32_t bytes) {
    asm volatile("mbarrier.arrive.expect_tx.shared::cta.b64 _, [%0], %1;" ::"r"(a), "r"(bytes) : "memory");
}
__device__ __forceinline__ void mbar_wait(uint32_t a, uint32_t parity) {
    asm volatile(
        "{\n\t"
        ".reg .pred P;\n\t"
        "WL%=:\n\t"
        "mbarrier.try_wait.parity.acquire.cta.shared::cta.b64 P, [%0], %1, 0x989680;\n\t"
        "@P bra WD%=;\n\t"
        "bra WL%=;\n\t"
        "WD%=:\n\t"
        "}" ::"r"(a), "r"(parity) : "memory");
}
__device__ __forceinline__ void bulk_g2s(uint32_t dst, const void* src, uint32_t bytes, uint32_t mbar) {
    asm volatile(
        "cp.async.bulk.shared::cluster.global.mbarrier::complete_tx::bytes [%0], [%1], %2, [%3];"
        ::"r"(dst), "l"(src), "r"(bytes), "r"(mbar) : "memory");
}
__device__ __forceinline__ void cp16(uint32_t dst, const void* src) {
    asm volatile("cp.async.cg.shared.global [%0], [%1], 16;" ::"r"(dst), "l"(src));
}
__device__ __forceinline__ void mma_bf16(float* d, const unsigned* a, const unsigned* b) {
    asm volatile(
        "mma.sync.aligned.m16n8k16.row.col.f32.bf16.bf16.f32 "
        "{%0,%1,%2,%3}, {%4,%5,%6,%7}, {%8,%9}, {%0,%1,%2,%3};"
        : "+f"(d[0]), "+f"(d[1]), "+f"(d[2]), "+f"(d[3])
        : "r"(a[0]), "r"(a[1]), "r"(a[2]), "r"(a[3]), "r"(b[0]), "r"(b[1]));
}
__device__ __forceinline__ float fsigmoid(float x) { return 1.0f / (1.0f + __expf(-x)); }
__device__ __forceinline__ float ftanh(float x)    { return 1.0f - 2.0f / (__expf(2.0f * x) + 1.0f); }

// ---------------- prep kernels ----------------
__global__ void zero_state_kernel() {
    int nh = 3 * 2 * Bsz * Uu;
    int nc = 3 * Bsz * Uu;
    __nv_bfloat16* h = &g_h[0][0][0];
    float* c = &g_c[0][0];
    for (int i = blockIdx.x * blockDim.x + threadIdx.x; i < nh; i += gridDim.x * blockDim.x)
        h[i] = __float2bfloat16(0.0f);
    for (int i = blockIdx.x * blockDim.x + threadIdx.x; i < nc; i += gridDim.x * blockDim.x)
        c[i] = 0.0f;
}

// Stable partition of batch rows by mask for each timestep.
__global__ void compact_kernel(const int* __restrict__ mask) {
    __shared__ int part[256];
    int t   = blockIdx.x;
    int tid = threadIdx.x;
    int ml[8], lc = 0;
#pragma unroll
    for (int j = 0; j < 8; j++) {
        int b = tid * 8 + j;
        ml[j] = (mask[b * Tt + t] != 0) ? 1 : 0;
        lc += ml[j];
    }
    part[tid] = lc;
    __syncthreads();
    for (int off = 1; off < 256; off <<= 1) {
        int v = (tid >= off) ? part[tid - off] : 0;
        __syncthreads();
        part[tid] += v;
        __syncthreads();
    }
    int incl  = part[tid];
    int base  = incl - lc;
    int total = part[255];
    int a = base, iv = tid * 8 - base;
#pragma unroll
    for (int j = 0; j < 8; j++) {
        int b = tid * 8 + j;
        if (ml[j]) g_order[t][a++]          = b;
        else       g_order[t][total + iv++] = b;
    }
    if (tid == 0) g_count[t] = total;
}

// Build tiled + SW128-preswizzled bf16 weight blocks. Block (nt,kt): 256 cols x 64 k.
__global__ void wprep_kernel(const float* __restrict__ W, const float* __restrict__ Uw, int layer) {
    int K   = (layer == 0) ? 512 : 1024;
    int Klo = (layer == 0) ? 0 : 512;
    int nkt = K / 64;
    char* dst = (char*)((layer == 0) ? g_w0 : ((layer == 1) ? g_w1 : g_w2));
    int totalPairs = K * G4 / 2;
    for (int idx = blockIdx.x * blockDim.x + threadIdx.x; idx < totalPairs;
         idx += gridDim.x * blockDim.x) {
        int klp = idx & 31;
        int c   = (idx >> 5) & 255;
        int blk = idx >> 13;
        int kt  = blk % nkt;
        int nt  = blk / nkt;
        int z   = (c >> 6) * 512 + nt * 64 + (c & 63);
        int kg  = kt * 64 + klp * 2;
        float v0, v1;
        if (kg < Klo) { v0 = W[kg * G4 + z]; v1 = W[(kg + 1) * G4 + z]; }
        else          { v0 = Uw[(kg - Klo) * G4 + z]; v1 = Uw[(kg + 1 - Klo) * G4 + z]; }
        uint32_t off = (uint32_t)(nt * nkt + kt) * B_BYTES + c * 128 +
                       (((uint32_t)klp * 4) ^ (((uint32_t)c & 7) * 16));
        *(__nv_bfloat162*)(dst + off) = __floats2bfloat162_rn(v0, v1);
    }
}

// ---------------- fused LSTM layer step (compacted rows) ----------------
__global__ void __launch_bounds__(THREADS, 2)
lstm_layer_kernel(const float* __restrict__ x, const int* __restrict__ mask,
                  const float* __restrict__ bias, const float* __restrict__ W0,
                  int layer, int t)
{
    const int nkt = (layer == 0) ? 8 : 16;
    const char* wB = (const char*)((layer == 0) ? g_w0 : ((layer == 1) ? g_w1 : g_w2));
    const int p = t & 1;
    const char* hOwnOld = (const char*)g_h[layer][p];
    char*       hOwnNew = (char*)g_h[layer][p ^ 1];
    const char* hLow    = (layer == 0) ? hOwnOld : (const char*)g_h[layer - 1][p ^ 1];
    float*      Cst     = g_c[layer];

    extern __shared__ char smem[];
    __shared__ __align__(16) uint64_t barmem[NS];
    __shared__ int ords[BM];

    const uint32_t sdata = ((uint32_t)__cvta_generic_to_shared(smem) + 1023u) & ~1023u;
    const uint32_t barb  = (uint32_t)__cvta_generic_to_shared(barmem);

    const int tid  = threadIdx.x;
    const int lane = tid & 31, warp = tid >> 5;
    const int colWarp = warp & 3, rowWarp = warp >> 2;
    const int g = lane >> 2, tig = lane & 3;
    const int nt   = blockIdx.x;
    const int row0 = blockIdx.y * BM;
    const int u0   = nt * 64;
    const int count = g_count[t];

    if (row0 >= count && nt != 0) return;

    if (tid < BM) ords[tid] = g_order[t][row0 + tid];
    if (tid == 0) {
        for (int s = 0; s < NS; s++) mbar_init(barb + 8 * s, 1);
        asm volatile("fence.proxy.async.shared::cta;" ::: "memory");
    }
    __syncthreads();

    if (row0 >= count) {
        // pure copy CTA (nt==0): h_new = h_old for these inactive rows
        for (int idx = tid; idx < BM * 64; idx += THREADS) {
            int r  = idx >> 6, ck = idx & 63;
            size_t off = (size_t)ords[r] * 1024 + ck * 16;
            *(uint4*)(hOwnNew + off) = *(const uint4*)(hOwnOld + off);
        }
        return;
    }

    // ---- producers ----
    auto issueA = [&](int kt, int s) {
        const char* base = (kt < 8) ? (hLow + (size_t)kt * 128)
                                    : (hOwnOld + (size_t)(kt - 8) * 128);
#pragma unroll
        for (int i = 0; i < 2; i++) {
            int c  = i * THREADS + tid;
            int r  = c >> 3, ck = c & 7;
            uint32_t dst = sdata + s * STAGE_BYTES + r * 128 +
                           (((uint32_t)ck * 16) ^ (((uint32_t)r & 7) * 16));
            cp16(dst, base + (size_t)ords[r] * 1024 + ck * 16);
        }
        asm volatile("cp.async.commit_group;");
    };
    auto issueB = [&](int kt, int s) {
        uint32_t full = barb + 8 * s;
        mbar_expect_tx(full, B_BYTES);
        bulk_g2s(sdata + s * STAGE_BYTES + A_BYTES,
                 wB + (size_t)(nt * nkt + kt) * B_BYTES, B_BYTES, full);
    };

    issueA(0, 0);
    if (tid == 0) issueB(0, 0);
    issueA(1, 1);
    if (tid == 0) issueB(1, 1);

    float acc[2][8][4];
#pragma unroll
    for (int m = 0; m < 2; m++)
#pragma unroll
        for (int j = 0; j < 8; j++)
#pragma unroll
            for (int r = 0; r < 4; r++) acc[m][j][r] = 0.0f;

    const uint32_t msk = (uint32_t)g * 16;

    for (int kt = 0; kt < nkt; kt++) {
        int s = kt & 1;
        asm volatile("cp.async.wait_group 1;");
        mbar_wait(barb + 8 * s, (uint32_t)((kt >> 1) & 1));
        __syncthreads();

        const char* As = smem + (sdata - (uint32_t)__cvta_generic_to_shared(smem)) + s * STAGE_BYTES;
        const char* Bs = As + A_BYTES;

#pragma unroll
        for (int kq = 0; kq < 4; kq++) {
            const uint32_t kb0 = (uint32_t)kq * 32 + (uint32_t)tig * 4;
            unsigned af[2][4];
#pragma unroll
            for (int m = 0; m < 2; m++) {
                int rb = rowWarp * 32 + m * 16 + g;
                const char* r0p = As + rb * 128;
                const char* r8p = r0p + 8 * 128;
                af[m][0] = *(const unsigned*)(r0p + (kb0 ^ msk));
                af[m][1] = *(const unsigned*)(r8p + (kb0 ^ msk));
                af[m][2] = *(const unsigned*)(r0p + ((kb0 + 16) ^ msk));
                af[m][3] = *(const unsigned*)(r8p + ((kb0 + 16) ^ msk));
            }
            unsigned bf[8][2];
#pragma unroll
            for (int j = 0; j < 8; j++) {
                int cb = (j >> 1) * 64 + colWarp * 16 + (j & 1) * 8 + g;
                const char* cp = Bs + cb * 128;
                bf[j][0] = *(const unsigned*)(cp + (kb0 ^ msk));
                bf[j][1] = *(const unsigned*)(cp + ((kb0 + 16) ^ msk));
            }
#pragma unroll
            for (int m = 0; m < 2; m++)
#pragma unroll
                for (int j = 0; j < 8; j++)
                    mma_bf16(acc[m][j], af[m], bf[j]);
        }
        __syncthreads();

        if (kt + NS < nkt) {
            issueA(kt + NS, s);
            if (tid == 0) issueB(kt + NS, s);
        }
    }

    // ---- fused epilogue ----
#pragma unroll
    for (int m = 0; m < 2; m++) {
#pragma unroll
        for (int rs = 0; rs < 2; rs++) {
            int ro = rowWarp * 32 + m * 16 + g + rs * 8;
            int bg = ords[ro];
            int mk = mask[bg * Tt + t];
            float xv = (layer == 0) ? x[bg * Tt + t] : 0.0f;
#pragma unroll
            for (int half = 0; half < 2; half++) {
                int u = u0 + colWarp * 16 + half * 8 + tig * 2;   // even
                size_t hoff = (size_t)bg * 1024 + (size_t)u * 2;
                __nv_bfloat162 hold2 = *(const __nv_bfloat162*)(hOwnOld + hoff);
                float2 c2 = *(const float2*)&Cst[bg * Uu + u];
                float cv[2] = {c2.x, c2.y}, hv[2];
#pragma unroll
                for (int pp = 0; pp < 2; pp++) {
                    int uu = u + pp;
                    int ri = rs * 2 + pp;
                    float zi = acc[m][0 + half][ri] + bias[uu];
                    float zf = acc[m][2 + half][ri] + bias[512 + uu];
                    float zg = acc[m][4 + half][ri] + bias[1024 + uu];
                    float zo = acc[m][6 + half][ri] + bias[1536 + uu];
                    if (layer == 0) {
                        zi += xv * W0[uu];
                        zf += xv * W0[512 + uu];
                        zg += xv * W0[1024 + uu];
                        zo += xv * W0[1536 + uu];
                    }
                    float co = cv[pp];
                    float ig = fsigmoid(zi);
                    float fg = fsigmoid(zf);
                    float gg = ftanh(zg);
                    float og = fsigmoid(zo);
                    float cn = fg * co + ig * gg;
                    float hn = og * ftanh(cn);
                    if (!mk) { cn = co; hn = __bfloat162float(pp ? hold2.y : hold2.x); }
                    cv[pp] = cn;
                    hv[pp] = hn;
                }
                *(float2*)&Cst[bg * Uu + u] = make_float2(cv[0], cv[1]);
                *(__nv_bfloat162*)(hOwnNew + hoff) = __floats2bfloat162_rn(hv[0], hv[1]);
            }
        }
    }
}

// ---------------- softmax head ----------------
__global__ void head_kernel(const float* __restrict__ Wd, const float* __restrict__ bd,
                            float* __restrict__ out)
{
    int gw   = (blockIdx.x * blockDim.x + threadIdx.x) >> 5;
    int lane = threadIdx.x & 31;
    if (gw >= Bsz) return;
    const __nv_bfloat16* h = g_h[2][0];   // T=100 even -> final states in buffer 0
    float a[Cc];
#pragma unroll
    for (int c = 0; c < Cc; c++) a[c] = 0.0f;
    for (int k = lane; k < Uu; k += 32) {
        float hv = __bfloat162float(h[(size_t)gw * Uu + k]);
#pragma unroll
        for (int c = 0; c < Cc; c++) a[c] += hv * Wd[k * Cc + c];
    }
#pragma unroll
    for (int c = 0; c < Cc; c++)
#pragma unroll
        for (int off = 16; off > 0; off >>= 1)
            a[c] += __shfl_xor_sync(0xffffffffu, a[c], off);
    if (lane == 0) {
        float logit[Cc], mx = -1e30f;
#pragma unroll
        for (int c = 0; c < Cc; c++) { logit[c] = a[c] + bd[c]; mx = fmaxf(mx, logit[c]); }
        float s = 0.0f;
#pragma unroll
        for (int c = 0; c < Cc; c++) { logit[c] = expf(logit[c] - mx); s += logit[c]; }
        float inv = 1.0f / s;
#pragma unroll
        for (int c = 0; c < Cc; c++) out[gw * Cc + c] = logit[c] * inv;
    }
}

// ---------------- launch ----------------
extern "C" void kernel_launch(void* const* d_in, const int* in_sizes, int n_in,
                              void* d_out, int out_size)
{
    const float* x    = (const float*)d_in[0];
    const int*   mask = (const int*)  d_in[1];
    const float* W0   = (const float*)d_in[2];
    const float* U0   = (const float*)d_in[3];
    const float* b0   = (const float*)d_in[4];
    const float* W1   = (const float*)d_in[5];
    const float* U1   = (const float*)d_in[6];
    const float* b1   = (const float*)d_in[7];
    const float* W2   = (const float*)d_in[8];
    const float* U2   = (const float*)d_in[9];
    const float* b2   = (const float*)d_in[10];
    const float* Wd   = (const float*)d_in[11];
    const float* bd   = (const float*)d_in[12];
    float* out = (float*)d_out;

    cudaFuncSetAttribute(lstm_layer_kernel, cudaFuncAttributeMaxDynamicSharedMemorySize,
                         SMEM_TOTAL);

    zero_state_kernel<<<256, 256>>>();
    wprep_kernel<<<256, 256>>>((const float*)0, U0, 0);
    wprep_kernel<<<512, 256>>>(W1, U1, 1);
    wprep_kernel<<<512, 256>>>(W2, U2, 2);
    compact_kernel<<<Tt, 256>>>(mask);

    dim3 grid(8, 32);   // 8 u-tiles x 32 row-tiles (compacted)
    for (int t = 0; t < Tt; t++) {
        lstm_layer_kernel<<<grid, THREADS, SMEM_TOTAL>>>(x, mask, b0, W0, 0, t);
        lstm_layer_kernel<<<grid, THREADS, SMEM_TOTAL>>>(x, mask, b1, (const float*)0, 1, t);
        lstm_layer_kernel<<<grid, THREADS, SMEM_TOTAL>>>(x, mask, b2, (const float*)0, 2, t);
    }
    head_kernel<<<(Bsz * 32 + 255) / 256, 256>>>(Wd, bd, out);
}

// round 6
// speedup vs baseline: 5.5277x; 1.2638x over previous
#include <cuda_runtime.h>
#include <cuda_bf16.h>
#include <cstdint>

#define Bsz 2048
#define Tt  100
#define Uu  512
#define Cc  10
#define G4  2048   // 4*U

#define BM      64       // compacted batch rows per CTA
#define THREADS 256      // 8 warps = 2 rowWarps x 4 colWarps
#define NS      2        // pipeline stages

#define A_BYTES 8192     // 64 rows x 128B (64 bf16 k)
#define B_BYTES 32768    // 256 cols x 128B
#define STAGE_BYTES (A_BYTES + B_BYTES)     // 40960
#define SMEM_TOTAL (NS * STAGE_BYTES + 1024)

// ---------------- device state ----------------
__device__ __nv_bfloat16 g_h[3][2][Bsz * Uu];                 // ping-pong h, PLAIN [b][512]
__device__ float         g_c[3][Bsz * Uu];                     // c fp32, linear
__device__ __align__(1024) __nv_bfloat16 g_w0[512  * G4];      // tiled+swizzled bf16 weights
__device__ __align__(1024) __nv_bfloat16 g_w1[1024 * G4];
__device__ __align__(1024) __nv_bfloat16 g_w2[1024 * G4];
__device__ int g_order[Tt][Bsz];                               // per-t: active rows, then inactive
__device__ int g_count[Tt];

// ---------------- helpers ----------------
__device__ __forceinline__ void mbar_init(uint32_t a, uint32_t cnt) {
    asm volatile("mbarrier.init.shared::cta.b64 [%0], %1;" ::"r"(a), "r"(cnt) : "memory");
}
__device__ __forceinline__ void mbar_expect_tx(uint32_t a, uint32_t bytes) {
    asm volatile("mbarrier.arrive.expect_tx.shared::cta.b64 _, [%0], %1;" ::"r"(a), "r"(bytes) : "memory");
}
__device__ __forceinline__ void mbar_wait(uint32_t a, uint32_t parity) {
    asm volatile(
        "{\n\t"
        ".reg .pred P;\n\t"
        "WL%=:\n\t"
        "mbarrier.try_wait.parity.acquire.cta.shared::cta.b64 P, [%0], %1, 0x989680;\n\t"
        "@P bra WD%=;\n\t"
        "bra WL%=;\n\t"
        "WD%=:\n\t"
        "}" ::"r"(a), "r"(parity) : "memory");
}
__device__ __forceinline__ void bulk_g2s(uint32_t dst, const void* src, uint32_t bytes, uint32_t mbar) {
    asm volatile(
        "cp.async.bulk.shared::cluster.global.mbarrier::complete_tx::bytes [%0], [%1], %2, [%3];"
        ::"r"(dst), "l"(src), "r"(bytes), "r"(mbar) : "memory");
}
__device__ __forceinline__ void cp16(uint32_t dst, const void* src) {
    asm volatile("cp.async.cg.shared.global [%0], [%1], 16;" ::"r"(dst), "l"(src));
}
__device__ __forceinline__ void mma_bf16(float* d, const unsigned* a, const unsigned* b) {
    asm volatile(
        "mma.sync.aligned.m16n8k16.row.col.f32.bf16.bf16.f32 "
        "{%0,%1,%2,%3}, {%4,%5,%6,%7}, {%8,%9}, {%0,%1,%2,%3};"
        : "+f"(d[0]), "+f"(d[1]), "+f"(d[2]), "+f"(d[3])
        : "r"(a[0]), "r"(a[1]), "r"(a[2]), "r"(a[3]), "r"(b[0]), "r"(b[1]));
}
__device__ __forceinline__ float fsigmoid(float x) { return 1.0f / (1.0f + __expf(-x)); }
__device__ __forceinline__ float ftanh(float x)    { return 1.0f - 2.0f / (__expf(2.0f * x) + 1.0f); }

// ---------------- prep kernels ----------------
__global__ void zero_state_kernel() {
    int nh = 3 * 2 * Bsz * Uu;
    int nc = 3 * Bsz * Uu;
    __nv_bfloat16* h = &g_h[0][0][0];
    float* c = &g_c[0][0];
    for (int i = blockIdx.x * blockDim.x + threadIdx.x; i < nh; i += gridDim.x * blockDim.x)
        h[i] = __float2bfloat16(0.0f);
    for (int i = blockIdx.x * blockDim.x + threadIdx.x; i < nc; i += gridDim.x * blockDim.x)
        c[i] = 0.0f;
}

// Stable partition of batch rows by mask for each timestep.
__global__ void compact_kernel(const int* __restrict__ mask) {
    __shared__ int part[256];
    int t   = blockIdx.x;
    int tid = threadIdx.x;
    int ml[8], lc = 0;
#pragma unroll
    for (int j = 0; j < 8; j++) {
        int b = tid * 8 + j;
        ml[j] = (mask[b * Tt + t] != 0) ? 1 : 0;
        lc += ml[j];
    }
    part[tid] = lc;
    __syncthreads();
    for (int off = 1; off < 256; off <<= 1) {
        int v = (tid >= off) ? part[tid - off] : 0;
        __syncthreads();
        part[tid] += v;
        __syncthreads();
    }
    int incl  = part[tid];
    int base  = incl - lc;
    int total = part[255];
    int a = base, iv = tid * 8 - base;
#pragma unroll
    for (int j = 0; j < 8; j++) {
        int b = tid * 8 + j;
        if (ml[j]) g_order[t][a++]          = b;
        else       g_order[t][total + iv++] = b;
    }
    if (tid == 0) g_count[t] = total;
}

// Build tiled + SW128-preswizzled bf16 weight blocks. Block (nt,kt): 256 cols x 64 k.
__global__ void wprep_kernel(const float* __restrict__ W, const float* __restrict__ Uw, int layer) {
    int K   = (layer == 0) ? 512 : 1024;
    int Klo = (layer == 0) ? 0 : 512;
    int nkt = K / 64;
    char* dst = (char*)((layer == 0) ? g_w0 : ((layer == 1) ? g_w1 : g_w2));
    int totalPairs = K * G4 / 2;
    for (int idx = blockIdx.x * blockDim.x + threadIdx.x; idx < totalPairs;
         idx += gridDim.x * blockDim.x) {
        int klp = idx & 31;
        int c   = (idx >> 5) & 255;
        int blk = idx >> 13;
        int kt  = blk % nkt;
        int nt  = blk / nkt;
        int z   = (c >> 6) * 512 + nt * 64 + (c & 63);
        int kg  = kt * 64 + klp * 2;
        float v0, v1;
        if (kg < Klo) { v0 = W[kg * G4 + z]; v1 = W[(kg + 1) * G4 + z]; }
        else          { v0 = Uw[(kg - Klo) * G4 + z]; v1 = Uw[(kg + 1 - Klo) * G4 + z]; }
        uint32_t off = (uint32_t)(nt * nkt + kt) * B_BYTES + c * 128 +
                       (((uint32_t)klp * 4) ^ (((uint32_t)c & 7) * 16));
        *(__nv_bfloat162*)(dst + off) = __floats2bfloat162_rn(v0, v1);
    }
}

// ---------------- fused LSTM diagonal step ----------------
// Diagonal d: layer = blockIdx.z processes t = d - layer. All three (layer, t)
// pairs in one launch are mutually independent (wavefront dependency proof:
// each reads only buffers written on diagonals <= d-1).
__global__ void __launch_bounds__(THREADS, 2)
lstm_diag_kernel(const float* __restrict__ x, const int* __restrict__ mask,
                 const float* __restrict__ b0, const float* __restrict__ b1,
                 const float* __restrict__ b2, const float* __restrict__ W0,
                 int d)
{
    const int layer = blockIdx.z;
    const int t = d - layer;
    if (t < 0 || t >= Tt) return;

    const int nkt = (layer == 0) ? 8 : 16;
    const char* wB = (const char*)((layer == 0) ? g_w0 : ((layer == 1) ? g_w1 : g_w2));
    const float* bias = (layer == 0) ? b0 : ((layer == 1) ? b1 : b2);
    const int p = t & 1;
    const char* hOwnOld = (const char*)g_h[layer][p];
    char*       hOwnNew = (char*)g_h[layer][p ^ 1];
    const char* hLow    = (layer == 0) ? hOwnOld : (const char*)g_h[layer - 1][p ^ 1];
    float*      Cst     = g_c[layer];

    extern __shared__ char smem[];
    __shared__ __align__(16) uint64_t barmem[NS];
    __shared__ int ords[BM];

    const uint32_t sdata = ((uint32_t)__cvta_generic_to_shared(smem) + 1023u) & ~1023u;
    const uint32_t barb  = (uint32_t)__cvta_generic_to_shared(barmem);

    const int tid  = threadIdx.x;
    const int lane = tid & 31, warp = tid >> 5;
    const int colWarp = warp & 3, rowWarp = warp >> 2;
    const int g = lane >> 2, tig = lane & 3;
    const int nt   = blockIdx.x;
    const int row0 = blockIdx.y * BM;
    const int u0   = nt * 64;
    const int count = g_count[t];

    if (row0 >= count && nt != 0) return;

    if (tid < BM) ords[tid] = g_order[t][row0 + tid];
    if (tid == 0) {
        for (int s = 0; s < NS; s++) mbar_init(barb + 8 * s, 1);
        asm volatile("fence.proxy.async.shared::cta;" ::: "memory");
    }
    __syncthreads();

    if (row0 >= count) {
        // pure copy CTA (nt==0): h_new = h_old for these inactive rows
        for (int idx = tid; idx < BM * 64; idx += THREADS) {
            int r  = idx >> 6, ck = idx & 63;
            size_t off = (size_t)ords[r] * 1024 + ck * 16;
            *(uint4*)(hOwnNew + off) = *(const uint4*)(hOwnOld + off);
        }
        return;
    }

    // ---- producers ----
    auto issueA = [&](int kt, int s) {
        const char* base = (kt < 8) ? (hLow + (size_t)kt * 128)
                                    : (hOwnOld + (size_t)(kt - 8) * 128);
#pragma unroll
        for (int i = 0; i < 2; i++) {
            int c  = i * THREADS + tid;
            int r  = c >> 3, ck = c & 7;
            uint32_t dst = sdata + s * STAGE_BYTES + r * 128 +
                           (((uint32_t)ck * 16) ^ (((uint32_t)r & 7) * 16));
            cp16(dst, base + (size_t)ords[r] * 1024 + ck * 16);
        }
        asm volatile("cp.async.commit_group;");
    };
    auto issueB = [&](int kt, int s) {
        uint32_t full = barb + 8 * s;
        mbar_expect_tx(full, B_BYTES);
        bulk_g2s(sdata + s * STAGE_BYTES + A_BYTES,
                 wB + (size_t)(nt * nkt + kt) * B_BYTES, B_BYTES, full);
    };

    issueA(0, 0);
    if (tid == 0) issueB(0, 0);
    issueA(1, 1);
    if (tid == 0) issueB(1, 1);

    float acc[2][8][4];
#pragma unroll
    for (int m = 0; m < 2; m++)
#pragma unroll
        for (int j = 0; j < 8; j++)
#pragma unroll
            for (int r = 0; r < 4; r++) acc[m][j][r] = 0.0f;

    const uint32_t msk = (uint32_t)g * 16;

    for (int kt = 0; kt < nkt; kt++) {
        int s = kt & 1;
        asm volatile("cp.async.wait_group 1;");
        mbar_wait(barb + 8 * s, (uint32_t)((kt >> 1) & 1));
        __syncthreads();

        const char* As = smem + (sdata - (uint32_t)__cvta_generic_to_shared(smem)) + s * STAGE_BYTES;
        const char* Bs = As + A_BYTES;

#pragma unroll
        for (int kq = 0; kq < 4; kq++) {
            const uint32_t kb0 = (uint32_t)kq * 32 + (uint32_t)tig * 4;
            unsigned af[2][4];
#pragma unroll
            for (int m = 0; m < 2; m++) {
                int rb = rowWarp * 32 + m * 16 + g;
                const char* r0p = As + rb * 128;
                const char* r8p = r0p + 8 * 128;
                af[m][0] = *(const unsigned*)(r0p + (kb0 ^ msk));
                af[m][1] = *(const unsigned*)(r8p + (kb0 ^ msk));
                af[m][2] = *(const unsigned*)(r0p + ((kb0 + 16) ^ msk));
                af[m][3] = *(const unsigned*)(r8p + ((kb0 + 16) ^ msk));
            }
            unsigned bf[8][2];
#pragma unroll
            for (int j = 0; j < 8; j++) {
                int cb = (j >> 1) * 64 + colWarp * 16 + (j & 1) * 8 + g;
                const char* cp = Bs + cb * 128;
                bf[j][0] = *(const unsigned*)(cp + (kb0 ^ msk));
                bf[j][1] = *(const unsigned*)(cp + ((kb0 + 16) ^ msk));
            }
#pragma unroll
            for (int m = 0; m < 2; m++)
#pragma unroll
                for (int j = 0; j < 8; j++)
                    mma_bf16(acc[m][j], af[m], bf[j]);
        }
        __syncthreads();

        if (kt + NS < nkt) {
            issueA(kt + NS, s);
            if (tid == 0) issueB(kt + NS, s);
        }
    }

    // ---- fused epilogue ----
#pragma unroll
    for (int m = 0; m < 2; m++) {
#pragma unroll
        for (int rs = 0; rs < 2; rs++) {
            int ro = rowWarp * 32 + m * 16 + g + rs * 8;
            int bg = ords[ro];
            int mk = mask[bg * Tt + t];
            float xv = (layer == 0) ? x[bg * Tt + t] : 0.0f;
#pragma unroll
            for (int half = 0; half < 2; half++) {
                int u = u0 + colWarp * 16 + half * 8 + tig * 2;   // even
                size_t hoff = (size_t)bg * 1024 + (size_t)u * 2;
                __nv_bfloat162 hold2 = *(const __nv_bfloat162*)(hOwnOld + hoff);
                float2 c2 = *(const float2*)&Cst[bg * Uu + u];
                float cv[2] = {c2.x, c2.y}, hv[2];
#pragma unroll
                for (int pp = 0; pp < 2; pp++) {
                    int uu = u + pp;
                    int ri = rs * 2 + pp;
                    float zi = acc[m][0 + half][ri] + bias[uu];
                    float zf = acc[m][2 + half][ri] + bias[512 + uu];
                    float zg = acc[m][4 + half][ri] + bias[1024 + uu];
                    float zo = acc[m][6 + half][ri] + bias[1536 + uu];
                    if (layer == 0) {
                        zi += xv * W0[uu];
                        zf += xv * W0[512 + uu];
                        zg += xv * W0[1024 + uu];
                        zo += xv * W0[1536 + uu];
                    }
                    float co = cv[pp];
                    float ig = fsigmoid(zi);
                    float fg = fsigmoid(zf);
                    float gg = ftanh(zg);
                    float og = fsigmoid(zo);
                    float cn = fg * co + ig * gg;
                    float hn = og * ftanh(cn);
                    if (!mk) { cn = co; hn = __bfloat162float(pp ? hold2.y : hold2.x); }
                    cv[pp] = cn;
                    hv[pp] = hn;
                }
                *(float2*)&Cst[bg * Uu + u] = make_float2(cv[0], cv[1]);
                *(__nv_bfloat162*)(hOwnNew + hoff) = __floats2bfloat162_rn(hv[0], hv[1]);
            }
        }
    }
}

// ---------------- softmax head ----------------
__global__ void head_kernel(const float* __restrict__ Wd, const float* __restrict__ bd,
                            float* __restrict__ out)
{
    int gw   = (blockIdx.x * blockDim.x + threadIdx.x) >> 5;
    int lane = threadIdx.x & 31;
    if (gw >= Bsz) return;
    const __nv_bfloat16* h = g_h[2][0];   // layer2 @ t=99 writes buffer (99&1)^1 = 0
    float a[Cc];
#pragma unroll
    for (int c = 0; c < Cc; c++) a[c] = 0.0f;
    for (int k = lane; k < Uu; k += 32) {
        float hv = __bfloat162float(h[(size_t)gw * Uu + k]);
#pragma unroll
        for (int c = 0; c < Cc; c++) a[c] += hv * Wd[k * Cc + c];
    }
#pragma unroll
    for (int c = 0; c < Cc; c++)
#pragma unroll
        for (int off = 16; off > 0; off >>= 1)
            a[c] += __shfl_xor_sync(0xffffffffu, a[c], off);
    if (lane == 0) {
        float logit[Cc], mx = -1e30f;
#pragma unroll
        for (int c = 0; c < Cc; c++) { logit[c] = a[c] + bd[c]; mx = fmaxf(mx, logit[c]); }
        float s = 0.0f;
#pragma unroll
        for (int c = 0; c < Cc; c++) { logit[c] = expf(logit[c] - mx); s += logit[c]; }
        float inv = 1.0f / s;
#pragma unroll
        for (int c = 0; c < Cc; c++) out[gw * Cc + c] = logit[c] * inv;
    }
}

// ---------------- launch ----------------
extern "C" void kernel_launch(void* const* d_in, const int* in_sizes, int n_in,
                              void* d_out, int out_size)
{
    const float* x    = (const float*)d_in[0];
    const int*   mask = (const int*)  d_in[1];
    const float* W0   = (const float*)d_in[2];
    const float* U0   = (const float*)d_in[3];
    const float* b0   = (const float*)d_in[4];
    const float* W1   = (const float*)d_in[5];
    const float* U1   = (const float*)d_in[6];
    const float* b1   = (const float*)d_in[7];
    const float* W2   = (const float*)d_in[8];
    const float* U2   = (const float*)d_in[9];
    const float* b2   = (const float*)d_in[10];
    const float* Wd   = (const float*)d_in[11];
    const float* bd   = (const float*)d_in[12];
    float* out = (float*)d_out;

    cudaFuncSetAttribute(lstm_diag_kernel, cudaFuncAttributeMaxDynamicSharedMemorySize,
                         SMEM_TOTAL);

    zero_state_kernel<<<256, 256>>>();
    wprep_kernel<<<256, 256>>>((const float*)0, U0, 0);
    wprep_kernel<<<512, 256>>>(W1, U1, 1);
    wprep_kernel<<<512, 256>>>(W2, U2, 2);
    compact_kernel<<<Tt, 256>>>(mask);

    dim3 grid(8, 32, 3);   // u-tiles x row-tiles x layers (wavefront diagonal)
    for (int d = 0; d <= Tt + 1; d++) {
        lstm_diag_kernel<<<grid, THREADS, SMEM_TOTAL>>>(x, mask, b0, b1, b2, W0, d);
    }
    head_kernel<<<(Bsz * 32 + 255) / 256, 256>>>(Wd, bd, out);
}